// round 3
// baseline (speedup 1.0000x reference)
#include <cuda_runtime.h>
#include <mma.h>
#include <type_traits>

using namespace nvcuda;

#define Bb 2
#define Ss 2048
#define Nn 4096
#define Dd 1024
#define Vv 32000
#define NLAYERS 6
#define LN_EPS 1e-5f
#define BSROWS (Bb * Ss) /* 4096 */

// ---------------- scratch (static device globals; no allocation) ----------
__device__ float g_v_hi[BSROWS * Dd], g_v_lo[BSROWS * Dd];
__device__ float g_x_hi[BSROWS * Nn], g_x_lo[BSROWS * Nn];
__device__ float g_kv_hi[Bb * Nn * Dd], g_kv_lo[Bb * Nn * Dd];
__device__ float g_a_hi[BSROWS * Dd], g_a_lo[BSROWS * Dd];
__device__ float g_y_hi[BSROWS * Nn], g_y_lo[BSROWS * Nn];
__device__ float g_t[BSROWS * Dd];
__device__ float g_Dx_hi[Dd * Nn], g_Dx_lo[Dd * Nn];
__device__ float g_Dy_hi[Dd * Nn], g_Dy_lo[Dd * Nn];
__device__ float g_E_hi[Nn * Dd], g_E_lo[Nn * Dd];

__device__ __forceinline__ float tf32r(float f) { return wmma::__float_to_tf32(f); }

// ---------------- weight split ------------------------------------------
__global__ void split_kernel(const float* __restrict__ w,
                             float* __restrict__ hi, float* __restrict__ lo) {
    size_t i = (size_t)blockIdx.x * blockDim.x + threadIdx.x;
    float4 s = ((const float4*)w)[i];
    float4 h, l;
    h.x = tf32r(s.x); l.x = tf32r(s.x - h.x);
    h.y = tf32r(s.y); l.y = tf32r(s.y - h.y);
    h.z = tf32r(s.z); l.z = tf32r(s.z - h.z);
    h.w = tf32r(s.w); l.w = tf32r(s.w - h.w);
    ((float4*)hi)[i] = h;
    ((float4*)lo)[i] = l;
}

// ---------------- embedding gather + split --------------------------------
__global__ void gather_kernel(const int* __restrict__ idx,
                              const float* __restrict__ emb,
                              float* __restrict__ vhi, float* __restrict__ vlo) {
    int row = blockIdx.x;
    int t = threadIdx.x;  // 256 threads, D/4 float4
    float4 s = ((const float4*)(emb + (size_t)idx[row] * Dd))[t];
    float4 h, l;
    h.x = tf32r(s.x); l.x = tf32r(s.x - h.x);
    h.y = tf32r(s.y); l.y = tf32r(s.y - h.y);
    h.z = tf32r(s.z); l.z = tf32r(s.z - h.z);
    h.w = tf32r(s.w); l.w = tf32r(s.w - h.w);
    ((float4*)(vhi + (size_t)row * Dd))[t] = h;
    ((float4*)(vlo + (size_t)row * Dd))[t] = l;
}

// ---------------- fused v = LN(v + LN(t)), split output -------------------
__device__ __forceinline__ void block_reduce2(float& s, float& s2, float* sh) {
#pragma unroll
    for (int o = 16; o > 0; o >>= 1) {
        s += __shfl_down_sync(0xFFFFFFFFu, s, o);
        s2 += __shfl_down_sync(0xFFFFFFFFu, s2, o);
    }
    int warp = threadIdx.x >> 5, lane = threadIdx.x & 31;
    if (lane == 0) { sh[warp * 2] = s; sh[warp * 2 + 1] = s2; }
    __syncthreads();
    float ts = 0.f, ts2 = 0.f;
#pragma unroll
    for (int w = 0; w < 8; w++) { ts += sh[w * 2]; ts2 += sh[w * 2 + 1]; }
    s = ts; s2 = ts2;
    __syncthreads();
}

__global__ void ln_res_ln_kernel(float* __restrict__ vhi, float* __restrict__ vlo,
                                 const float* __restrict__ t) {
    __shared__ float sh[16];
    int row = blockIdx.x;
    int tid = threadIdx.x;
    const float4 tv = ((const float4*)(t + (size_t)row * Dd))[tid];
    float4 vh = ((float4*)(vhi + (size_t)row * Dd))[tid];
    float4 vl = ((float4*)(vlo + (size_t)row * Dd))[tid];

    float s = tv.x + tv.y + tv.z + tv.w;
    float s2 = tv.x * tv.x + tv.y * tv.y + tv.z * tv.z + tv.w * tv.w;
    block_reduce2(s, s2, sh);
    float m = s * (1.0f / Dd);
    float inv = rsqrtf(s2 * (1.0f / Dd) - m * m + LN_EPS);

    float4 u;
    u.x = (vh.x + vl.x) + (tv.x - m) * inv;
    u.y = (vh.y + vl.y) + (tv.y - m) * inv;
    u.z = (vh.z + vl.z) + (tv.z - m) * inv;
    u.w = (vh.w + vl.w) + (tv.w - m) * inv;

    s = u.x + u.y + u.z + u.w;
    s2 = u.x * u.x + u.y * u.y + u.z * u.z + u.w * u.w;
    block_reduce2(s, s2, sh);
    m = s * (1.0f / Dd);
    inv = rsqrtf(s2 * (1.0f / Dd) - m * m + LN_EPS);

    float4 r, h, l;
    r.x = (u.x - m) * inv; r.y = (u.y - m) * inv;
    r.z = (u.z - m) * inv; r.w = (u.w - m) * inv;
    h.x = tf32r(r.x); l.x = tf32r(r.x - h.x);
    h.y = tf32r(r.y); l.y = tf32r(r.y - h.y);
    h.z = tf32r(r.z); l.z = tf32r(r.z - h.z);
    h.w = tf32r(r.w); l.w = tf32r(r.w - h.w);
    ((float4*)(vhi + (size_t)row * Dd))[tid] = h;
    ((float4*)(vlo + (size_t)row * Dd))[tid] = l;
}

// ---------------- cp.async helpers ----------------------------------------
__device__ __forceinline__ void cpa16(float* s, const float* g) {
    asm volatile("cp.async.cg.shared.global [%0],[%1],16;\n" ::
                 "r"((unsigned)__cvta_generic_to_shared(s)), "l"(g));
}
__device__ __forceinline__ void cpa_commit() {
    asm volatile("cp.async.commit_group;\n");
}

// ---------------- split-precision TF32 GEMM --------------------------------
// C = op(A) @ B, A/B given as (hi, lo) tf32-rounded pairs. NMMA=3: full 3xTF32
// (AhiBhi + AhiBlo + AloBhi). NMMA=1: AhiBhi only (B raw, rounded on load).
// WLO=true: write (Chi, Clo) split outputs; else raw fp32 to Chi.
// EPI: 0 none, 1 relu, 2 relu * (AuxHi+AuxLo).
constexpr int BM = 128, BN = 64, BK = 16;
enum { EPI_NONE = 0, EPI_RELU = 1, EPI_RELU_MUL = 2 };

constexpr int LDA_NT = BK + 4;   // 20
constexpr int LDA_T  = BM + 4;   // 132
constexpr int LDB    = BN + 4;   // 68
constexpr int SA_NT = BM * LDA_NT;   // 2560
constexpr int SA_T  = BK * LDA_T;    // 2112
constexpr int SB    = BK * LDB;      // 1088

constexpr int SMEM_NT_BYTES = 2 * (2 * SA_NT + 2 * SB) * 4;  // 58368
constexpr int SMEM_T_BYTES  = 2 * (2 * SA_T  + 2 * SB) * 4;  // 51200

template <bool TRANSA, int EPI, int NMMA, bool WLO>
__global__ void __launch_bounds__(256, 2)
gemm_split(const float* __restrict__ Ahi, const float* __restrict__ Alo,
           const float* __restrict__ Bhi, const float* __restrict__ Blo,
           float* __restrict__ Chi, float* __restrict__ Clo,
           const float* __restrict__ AuxHi, const float* __restrict__ AuxLo,
           int M, int Ncol, int K, long sA, long sB, long sC) {
    extern __shared__ float smem[];
    constexpr int SA = TRANSA ? SA_T : SA_NT;
    constexpr int STAGE = 2 * SA + 2 * SB;
    __shared__ __align__(16) float EpiS[(EPI == EPI_RELU_MUL) ? (8 * 16 * 20) : 8];

    const int bz = blockIdx.z;
    Ahi += (long)bz * sA;
    Bhi += (long)bz * sB;
    Chi += (long)bz * sC;
    if (NMMA == 3) { Alo += (long)bz * sA; Blo += (long)bz * sB; }

    const int rowBase = blockIdx.y * BM;
    const int colBase = blockIdx.x * BN;
    const int tid = threadIdx.x;
    const int warpId = tid >> 5;
    const int lane = tid & 31;
    const int wr = warpId >> 1;  // 0..3
    const int wc = warpId & 1;   // 0..1

    const int lda = TRANSA ? M : K;
    const int ldb = Ncol;
    const int ldc = Ncol;

    // load index split
    const int arow = tid >> 1;           // NT: 0..127
    const int acol = (tid & 1) * 8;      // NT: float col 0 or 8
    const int tkr = tid >> 4;            // T: k row 0..15
    const int tmc = (tid & 15) * 8;      // T: m col, 8 floats per thread
    const int brow = tid >> 4;           // 0..15
    const int bcol = (tid & 15) * 4;     // 0..60

    auto loadStage = [&](int s, int kBase) {
        float* aH = smem + s * STAGE;
        float* aL = aH + SA;
        float* bH = aL + SA;
        float* bL = bH + SB;
        if constexpr (!TRANSA) {
            const float* gh = Ahi + (long)(rowBase + arow) * lda + kBase + acol;
            cpa16(aH + arow * LDA_NT + acol, gh);
            cpa16(aH + arow * LDA_NT + acol + 4, gh + 4);
            if constexpr (NMMA == 3) {
                const float* gl = Alo + (long)(rowBase + arow) * lda + kBase + acol;
                cpa16(aL + arow * LDA_NT + acol, gl);
                cpa16(aL + arow * LDA_NT + acol + 4, gl + 4);
            }
        } else {
            const float* gh = Ahi + (long)(kBase + tkr) * lda + rowBase + tmc;
            cpa16(aH + tkr * LDA_T + tmc, gh);
            cpa16(aH + tkr * LDA_T + tmc + 4, gh + 4);
            if constexpr (NMMA == 3) {
                const float* gl = Alo + (long)(kBase + tkr) * lda + rowBase + tmc;
                cpa16(aL + tkr * LDA_T + tmc, gl);
                cpa16(aL + tkr * LDA_T + tmc + 4, gl + 4);
            }
        }
        cpa16(bH + brow * LDB + bcol, Bhi + (long)(kBase + brow) * ldb + colBase + bcol);
        if constexpr (NMMA == 3)
            cpa16(bL + brow * LDB + bcol, Blo + (long)(kBase + brow) * ldb + colBase + bcol);
    };

    using ALayout = typename std::conditional<TRANSA, wmma::col_major, wmma::row_major>::type;
    using AFrag = wmma::fragment<wmma::matrix_a, 16, 16, 8, wmma::precision::tf32, ALayout>;
    using BFrag = wmma::fragment<wmma::matrix_b, 16, 16, 8, wmma::precision::tf32, wmma::row_major>;
    using CFrag = wmma::fragment<wmma::accumulator, 16, 16, 8, float>;

    CFrag acc[2][2];
#pragma unroll
    for (int i = 0; i < 2; i++)
#pragma unroll
        for (int j = 0; j < 2; j++) wmma::fill_fragment(acc[i][j], 0.0f);

    const int KT = K / BK;

    loadStage(0, 0);
    cpa_commit();

    for (int kt = 0; kt < KT; kt++) {
        const int cur = kt & 1;
        if (kt + 1 < KT) {
            loadStage(cur ^ 1, (kt + 1) * BK);
            cpa_commit();
            asm volatile("cp.async.wait_group 1;\n");
        } else {
            asm volatile("cp.async.wait_group 0;\n");
        }
        __syncthreads();

        const float* aH = smem + cur * STAGE;
        const float* aL = aH + SA;
        const float* bH = aL + SA;
        const float* bL = bH + SB;

#pragma unroll
        for (int kk = 0; kk < BK / 8; kk++) {
            AFrag afh[2], afl[2];
            BFrag bfh[2], bfl[2];
#pragma unroll
            for (int i = 0; i < 2; i++) {
                if constexpr (!TRANSA) {
                    wmma::load_matrix_sync(afh[i], aH + (wr * 32 + i * 16) * LDA_NT + kk * 8, LDA_NT);
                    if constexpr (NMMA == 3)
                        wmma::load_matrix_sync(afl[i], aL + (wr * 32 + i * 16) * LDA_NT + kk * 8, LDA_NT);
                } else {
                    wmma::load_matrix_sync(afh[i], aH + (kk * 8) * LDA_T + wr * 32 + i * 16, LDA_T);
                    if constexpr (NMMA == 3)
                        wmma::load_matrix_sync(afl[i], aL + (kk * 8) * LDA_T + wr * 32 + i * 16, LDA_T);
                }
            }
#pragma unroll
            for (int j = 0; j < 2; j++) {
                wmma::load_matrix_sync(bfh[j], bH + (kk * 8) * LDB + wc * 32 + j * 16, LDB);
                if constexpr (NMMA == 3) {
                    wmma::load_matrix_sync(bfl[j], bL + (kk * 8) * LDB + wc * 32 + j * 16, LDB);
                } else {
                    // raw B: round to tf32 on the fly
#pragma unroll
                    for (int e = 0; e < bfh[j].num_elements; e++)
                        bfh[j].x[e] = tf32r(bfh[j].x[e]);
                }
            }
            if constexpr (NMMA == 3) {
#pragma unroll
                for (int i = 0; i < 2; i++)
#pragma unroll
                    for (int j = 0; j < 2; j++)
                        wmma::mma_sync(acc[i][j], afh[i], bfl[j], acc[i][j]);
#pragma unroll
                for (int i = 0; i < 2; i++)
#pragma unroll
                    for (int j = 0; j < 2; j++)
                        wmma::mma_sync(acc[i][j], afl[i], bfh[j], acc[i][j]);
            }
#pragma unroll
            for (int i = 0; i < 2; i++)
#pragma unroll
                for (int j = 0; j < 2; j++)
                    wmma::mma_sync(acc[i][j], afh[i], bfh[j], acc[i][j]);
        }
        __syncthreads();
    }

    // ------------- epilogue -------------
    if constexpr (EPI == EPI_NONE || EPI == EPI_RELU) {
        CFrag th, tl;
#pragma unroll
        for (int i = 0; i < 2; i++)
#pragma unroll
            for (int j = 0; j < 2; j++) {
                float* dst = Chi + (long)(rowBase + wr * 32 + i * 16) * ldc + colBase + wc * 32 + j * 16;
                if constexpr (!WLO) {
                    if constexpr (EPI == EPI_RELU) {
#pragma unroll
                        for (int e = 0; e < acc[i][j].num_elements; e++)
                            acc[i][j].x[e] = fmaxf(acc[i][j].x[e], 0.0f);
                    }
                    wmma::store_matrix_sync(dst, acc[i][j], ldc, wmma::mem_row_major);
                } else {
#pragma unroll
                    for (int e = 0; e < acc[i][j].num_elements; e++) {
                        float c = acc[i][j].x[e];
                        if constexpr (EPI == EPI_RELU) c = fmaxf(c, 0.0f);
                        float h = tf32r(c);
                        th.x[e] = h;
                        tl.x[e] = tf32r(c - h);
                    }
                    wmma::store_matrix_sync(dst, th, ldc, wmma::mem_row_major);
                    float* dstL = Clo + (long)bz * sC +
                                  (long)(rowBase + wr * 32 + i * 16) * ldc + colBase + wc * 32 + j * 16;
                    wmma::store_matrix_sync(dstL, tl, ldc, wmma::mem_row_major);
                }
            }
    } else {
        // relu(acc) * (AuxHi + AuxLo), write hi/lo
        float* patch = &EpiS[warpId * 16 * 20];
        const int rr = lane >> 1;
        const int cc = (lane & 1) * 8;
#pragma unroll
        for (int i = 0; i < 2; i++)
#pragma unroll
            for (int j = 0; j < 2; j++) {
                wmma::store_matrix_sync(patch, acc[i][j], 20, wmma::mem_row_major);
                __syncwarp();
                long gr = rowBase + wr * 32 + i * 16 + rr;
                long gc = colBase + wc * 32 + j * 16 + cc;
                float4 xh0 = *(const float4*)(AuxHi + gr * ldc + gc);
                float4 xh1 = *(const float4*)(AuxHi + gr * ldc + gc + 4);
                float4 xl0 = *(const float4*)(AuxLo + gr * ldc + gc);
                float4 xl1 = *(const float4*)(AuxLo + gr * ldc + gc + 4);
                float xf[8] = {xh0.x + xl0.x, xh0.y + xl0.y, xh0.z + xl0.z, xh0.w + xl0.w,
                               xh1.x + xl1.x, xh1.y + xl1.y, xh1.z + xl1.z, xh1.w + xl1.w};
                float h[8], l[8];
#pragma unroll
                for (int q = 0; q < 8; q++) {
                    float c = fmaxf(patch[rr * 20 + cc + q], 0.0f) * xf[q];
                    h[q] = tf32r(c);
                    l[q] = tf32r(c - h[q]);
                }
                *(float4*)(Chi + gr * ldc + gc) = make_float4(h[0], h[1], h[2], h[3]);
                *(float4*)(Chi + gr * ldc + gc + 4) = make_float4(h[4], h[5], h[6], h[7]);
                *(float4*)(Clo + gr * ldc + gc) = make_float4(l[0], l[1], l[2], l[3]);
                *(float4*)(Clo + gr * ldc + gc + 4) = make_float4(l[4], l[5], l[6], l[7]);
                __syncwarp();
            }
    }
}

// ---------------- launch -----------------------------------------------
extern "C" void kernel_launch(void* const* d_in, const int* in_sizes, int n_in,
                              void* d_out, int out_size) {
    const int* idx = (const int*)d_in[0];
    const float* emb = (const float*)d_in[1];
    const float* Dx = (const float*)d_in[2];
    const float* Dy = (const float*)d_in[3];
    const float* E = (const float*)d_in[4];
    const float* readout = (const float*)d_in[5];
    float* out = (float*)d_out;

    float *vh, *vl, *xh, *xl, *kvh, *kvl, *ah, *al, *yh, *yl, *t;
    float *dxh, *dxl, *dyh, *dyl, *eh, *el;
    cudaGetSymbolAddress((void**)&vh, g_v_hi);
    cudaGetSymbolAddress((void**)&vl, g_v_lo);
    cudaGetSymbolAddress((void**)&xh, g_x_hi);
    cudaGetSymbolAddress((void**)&xl, g_x_lo);
    cudaGetSymbolAddress((void**)&kvh, g_kv_hi);
    cudaGetSymbolAddress((void**)&kvl, g_kv_lo);
    cudaGetSymbolAddress((void**)&ah, g_a_hi);
    cudaGetSymbolAddress((void**)&al, g_a_lo);
    cudaGetSymbolAddress((void**)&yh, g_y_hi);
    cudaGetSymbolAddress((void**)&yl, g_y_lo);
    cudaGetSymbolAddress((void**)&t, g_t);
    cudaGetSymbolAddress((void**)&dxh, g_Dx_hi);
    cudaGetSymbolAddress((void**)&dxl, g_Dx_lo);
    cudaGetSymbolAddress((void**)&dyh, g_Dy_hi);
    cudaGetSymbolAddress((void**)&dyl, g_Dy_lo);
    cudaGetSymbolAddress((void**)&eh, g_E_hi);
    cudaGetSymbolAddress((void**)&el, g_E_lo);

    // opt in to >48KB dynamic smem (host-side attr set; not a stream op)
    cudaFuncSetAttribute(gemm_split<false, EPI_RELU, 3, true>,
                         cudaFuncAttributeMaxDynamicSharedMemorySize, SMEM_NT_BYTES);
    cudaFuncSetAttribute(gemm_split<true, EPI_NONE, 3, true>,
                         cudaFuncAttributeMaxDynamicSharedMemorySize, SMEM_T_BYTES);
    cudaFuncSetAttribute(gemm_split<false, EPI_NONE, 3, true>,
                         cudaFuncAttributeMaxDynamicSharedMemorySize, SMEM_NT_BYTES);
    cudaFuncSetAttribute(gemm_split<false, EPI_RELU_MUL, 3, true>,
                         cudaFuncAttributeMaxDynamicSharedMemorySize, SMEM_NT_BYTES);
    cudaFuncSetAttribute(gemm_split<false, EPI_NONE, 3, false>,
                         cudaFuncAttributeMaxDynamicSharedMemorySize, SMEM_NT_BYTES);
    cudaFuncSetAttribute(gemm_split<false, EPI_NONE, 1, false>,
                         cudaFuncAttributeMaxDynamicSharedMemorySize, SMEM_NT_BYTES);

    // split weights (once per launch; deterministic)
    split_kernel<<<(Dd * Nn) / 1024, 256>>>(Dx, dxh, dxl);
    split_kernel<<<(Dd * Nn) / 1024, 256>>>(Dy, dyh, dyl);
    split_kernel<<<(Nn * Dd) / 1024, 256>>>(E, eh, el);

    // v = emb[input], split
    gather_kernel<<<BSROWS, 256>>>(idx, emb, vh, vl);

    for (int l = 0; l < NLAYERS; l++) {
        // x = relu(v @ Dx)
        gemm_split<false, EPI_RELU, 3, true><<<dim3(Nn / BN, BSROWS / BM, 1), 256, SMEM_NT_BYTES>>>(
            vh, vl, dxh, dxl, xh, xl, nullptr, nullptr, BSROWS, Nn, Dd, 0, 0, 0);

        // kv = x^T @ v per batch
        gemm_split<true, EPI_NONE, 3, true><<<dim3(Dd / BN, Nn / BM, Bb), 256, SMEM_T_BYTES>>>(
            xh, xl, vh, vl, kvh, kvl, nullptr, nullptr, Nn, Dd, Ss,
            (long)Ss * Nn, (long)Ss * Dd, (long)Nn * Dd);

        // a = x @ kv per batch
        gemm_split<false, EPI_NONE, 3, true><<<dim3(Dd / BN, Ss / BM, Bb), 256, SMEM_NT_BYTES>>>(
            xh, xl, kvh, kvl, ah, al, nullptr, nullptr, Ss, Dd, Nn,
            (long)Ss * Nn, (long)Nn * Dd, (long)Ss * Dd);

        // y = relu(a @ Dy) * x
        gemm_split<false, EPI_RELU_MUL, 3, true><<<dim3(Nn / BN, BSROWS / BM, 1), 256, SMEM_NT_BYTES>>>(
            ah, al, dyh, dyl, yh, yl, xh, xl, BSROWS, Nn, Dd, 0, 0, 0);

        // t = y @ E  (plain fp32 output)
        gemm_split<false, EPI_NONE, 3, false><<<dim3(Dd / BN, BSROWS / BM, 1), 256, SMEM_NT_BYTES>>>(
            yh, yl, eh, el, t, nullptr, nullptr, nullptr, BSROWS, Dd, Nn, 0, 0, 0);

        // v = LN(v + LN(t)), split output
        ln_res_ln_kernel<<<BSROWS, 256>>>(vh, vl, t);
    }

    // out = v_hi @ readout (1xTF32)
    gemm_split<false, EPI_NONE, 1, false><<<dim3(Vv / BN, BSROWS / BM, 1), 256, SMEM_NT_BYTES>>>(
        vh, nullptr, readout, nullptr, out, nullptr, nullptr, nullptr, BSROWS, Vv, Dd, 0, 0, 0);
}

// round 4
// speedup vs baseline: 2.6952x; 2.6952x over previous
#include <cuda_runtime.h>
#include <cuda_bf16.h>
#include <mma.h>
#include <type_traits>

using namespace nvcuda;
typedef __nv_bfloat16 bf16;

#define Bb 2
#define Ss 2048
#define Nn 4096
#define Dd 1024
#define Vv 32000
#define NLAYERS 6
#define LN_EPS 1e-5f
#define BSROWS (Bb * Ss) /* 4096 */

// ---------------- scratch (static device globals; no allocation) ----------
__device__ __align__(16) bf16 g_v_hi[BSROWS * Dd], g_v_lo[BSROWS * Dd];
__device__ __align__(16) bf16 g_x_hi[BSROWS * Nn], g_x_lo[BSROWS * Nn];
__device__ __align__(16) bf16 g_kv_hi[Bb * Nn * Dd], g_kv_lo[Bb * Nn * Dd];
__device__ __align__(16) bf16 g_a_hi[BSROWS * Dd], g_a_lo[BSROWS * Dd];
__device__ __align__(16) bf16 g_y_hi[BSROWS * Nn], g_y_lo[BSROWS * Nn];
__device__ __align__(16) float g_t[BSROWS * Dd];
__device__ __align__(16) bf16 g_Dx_hi[Dd * Nn], g_Dx_lo[Dd * Nn];
__device__ __align__(16) bf16 g_Dy_hi[Dd * Nn], g_Dy_lo[Dd * Nn];
__device__ __align__(16) bf16 g_E_hi[Nn * Dd], g_E_lo[Nn * Dd];
__device__ __align__(16) bf16 g_R_hi[(size_t)Dd * Vv], g_R_lo[(size_t)Dd * Vv];

__device__ __forceinline__ void bsplit(float f, bf16& h, bf16& l) {
    h = __float2bfloat16(f);
    l = __float2bfloat16(f - __bfloat162float(h));
}

// ---------------- weight split (fp32 -> bf16 hi/lo), 8 elems/thread -------
__global__ void split_kernel(const float* __restrict__ w,
                             bf16* __restrict__ hi, bf16* __restrict__ lo) {
    size_t i = (size_t)blockIdx.x * blockDim.x + threadIdx.x;
    float4 s0 = ((const float4*)w)[2 * i];
    float4 s1 = ((const float4*)w)[2 * i + 1];
    bf16 h[8], l[8];
    bsplit(s0.x, h[0], l[0]); bsplit(s0.y, h[1], l[1]);
    bsplit(s0.z, h[2], l[2]); bsplit(s0.w, h[3], l[3]);
    bsplit(s1.x, h[4], l[4]); bsplit(s1.y, h[5], l[5]);
    bsplit(s1.z, h[6], l[6]); bsplit(s1.w, h[7], l[7]);
    ((uint4*)hi)[i] = *(uint4*)h;
    ((uint4*)lo)[i] = *(uint4*)l;
}

// ---------------- embedding gather + split --------------------------------
__global__ void gather_kernel(const int* __restrict__ idx,
                              const float* __restrict__ emb,
                              bf16* __restrict__ vhi, bf16* __restrict__ vlo) {
    int row = blockIdx.x;
    int t = threadIdx.x;  // 256 threads, 4 elems each
    float4 s = ((const float4*)(emb + (size_t)idx[row] * Dd))[t];
    bf16 h[4], l[4];
    bsplit(s.x, h[0], l[0]); bsplit(s.y, h[1], l[1]);
    bsplit(s.z, h[2], l[2]); bsplit(s.w, h[3], l[3]);
    ((uint2*)(vhi + (size_t)row * Dd))[t] = *(uint2*)h;
    ((uint2*)(vlo + (size_t)row * Dd))[t] = *(uint2*)l;
}

// ---------------- fused v = LN(v + LN(t)), bf16 hi/lo state ----------------
__device__ __forceinline__ void block_reduce2(float& s, float& s2, float* sh) {
#pragma unroll
    for (int o = 16; o > 0; o >>= 1) {
        s += __shfl_down_sync(0xFFFFFFFFu, s, o);
        s2 += __shfl_down_sync(0xFFFFFFFFu, s2, o);
    }
    int warp = threadIdx.x >> 5, lane = threadIdx.x & 31;
    if (lane == 0) { sh[warp * 2] = s; sh[warp * 2 + 1] = s2; }
    __syncthreads();
    float ts = 0.f, ts2 = 0.f;
#pragma unroll
    for (int w = 0; w < 8; w++) { ts += sh[w * 2]; ts2 += sh[w * 2 + 1]; }
    s = ts; s2 = ts2;
    __syncthreads();
}

__global__ void ln_res_ln_kernel(bf16* __restrict__ vhi, bf16* __restrict__ vlo,
                                 const float* __restrict__ t) {
    __shared__ float sh[16];
    int row = blockIdx.x;
    int tid = threadIdx.x;
    const float4 tv = ((const float4*)(t + (size_t)row * Dd))[tid];
    uint2 vhu = ((const uint2*)(vhi + (size_t)row * Dd))[tid];
    uint2 vlu = ((const uint2*)(vlo + (size_t)row * Dd))[tid];
    const bf16* vhp = (const bf16*)&vhu;
    const bf16* vlp = (const bf16*)&vlu;

    float s = tv.x + tv.y + tv.z + tv.w;
    float s2 = tv.x * tv.x + tv.y * tv.y + tv.z * tv.z + tv.w * tv.w;
    block_reduce2(s, s2, sh);
    float m = s * (1.0f / Dd);
    float inv = rsqrtf(s2 * (1.0f / Dd) - m * m + LN_EPS);

    float u[4];
    u[0] = (__bfloat162float(vhp[0]) + __bfloat162float(vlp[0])) + (tv.x - m) * inv;
    u[1] = (__bfloat162float(vhp[1]) + __bfloat162float(vlp[1])) + (tv.y - m) * inv;
    u[2] = (__bfloat162float(vhp[2]) + __bfloat162float(vlp[2])) + (tv.z - m) * inv;
    u[3] = (__bfloat162float(vhp[3]) + __bfloat162float(vlp[3])) + (tv.w - m) * inv;

    s = u[0] + u[1] + u[2] + u[3];
    s2 = u[0] * u[0] + u[1] * u[1] + u[2] * u[2] + u[3] * u[3];
    block_reduce2(s, s2, sh);
    m = s * (1.0f / Dd);
    inv = rsqrtf(s2 * (1.0f / Dd) - m * m + LN_EPS);

    bf16 h[4], l[4];
#pragma unroll
    for (int q = 0; q < 4; q++) bsplit((u[q] - m) * inv, h[q], l[q]);
    ((uint2*)(vhi + (size_t)row * Dd))[tid] = *(uint2*)h;
    ((uint2*)(vlo + (size_t)row * Dd))[tid] = *(uint2*)l;
}

// ---------------- cp.async helpers ----------------------------------------
__device__ __forceinline__ void cpa16(bf16* s, const bf16* g) {
    asm volatile("cp.async.cg.shared.global [%0],[%1],16;\n" ::
                 "r"((unsigned)__cvta_generic_to_shared(s)), "l"(g));
}
__device__ __forceinline__ void cpa_commit() {
    asm volatile("cp.async.commit_group;\n");
}

// ---------------- 3xBF16 split GEMM ----------------------------------------
// C = op(A) @ B where A,B are bf16 (hi,lo) pairs; acc fp32; 3 MMA terms:
// AhiBhi + AhiBlo + AloBhi.  TRANSA=1: A stored [K,M] row-major.
// EPI: 0 none, 1 relu, 2 relu*(AuxHi+AuxLo).  WLO: write bf16 hi/lo else fp32.
constexpr int BM = 128, BN = 64, BK = 32;
enum { EPI_NONE = 0, EPI_RELU = 1, EPI_RELU_MUL = 2 };

constexpr int LDA_NT = BK + 8;    // 40 bf16
constexpr int LDA_T  = BM + 8;    // 136
constexpr int LDBs   = BN + 8;    // 72
constexpr int SA_NT = BM * LDA_NT;  // 5120 elems
constexpr int SA_T  = BK * LDA_T;   // 4352
constexpr int SBn   = BK * LDBs;    // 2304

constexpr int SMEM_NT_BYTES = 2 * (2 * SA_NT + 2 * SBn) * 2;  // 59392
constexpr int SMEM_T_BYTES  = 2 * (2 * SA_T + 2 * SBn) * 2;   // 53248

template <bool TRANSA, int EPI, bool WLO>
__global__ void __launch_bounds__(256, 2)
gemm_bf16x3(const bf16* __restrict__ Ahi, const bf16* __restrict__ Alo,
            const bf16* __restrict__ Bhi, const bf16* __restrict__ Blo,
            float* __restrict__ Cf, bf16* __restrict__ Chi, bf16* __restrict__ Clo,
            const bf16* __restrict__ AuxHi, const bf16* __restrict__ AuxLo,
            int M, int Ncol, int K, long sA, long sB, long sC) {
    extern __shared__ bf16 smem[];
    constexpr int SA = TRANSA ? SA_T : SA_NT;
    constexpr int STAGE = 2 * SA + 2 * SBn;

    const int bz = blockIdx.z;
    Ahi += (long)bz * sA;
    Alo += (long)bz * sA;
    Bhi += (long)bz * sB;
    Blo += (long)bz * sB;

    const int rowBase = blockIdx.y * BM;
    const int colBase = blockIdx.x * BN;
    const int tid = threadIdx.x;
    const int warpId = tid >> 5;
    const int lane = tid & 31;
    const int wr = warpId >> 1;  // 0..3
    const int wc = warpId & 1;   // 0..1

    const int lda = TRANSA ? M : K;
    const int ldb = Ncol;
    const int ldc = Ncol;

    // global->smem index split
    const int arow = tid >> 1;          // NT: 0..127
    const int acol = (tid & 1) * 16;    // NT: 0 or 16
    const int tkr = tid >> 3;           // T: 0..31
    const int tmc = (tid & 7) * 16;     // T: 0..112
    const int brow = tid >> 3;          // 0..31
    const int bcol = (tid & 7) * 8;     // 0..56

    auto loadStage = [&](int s, int kBase) {
        bf16* aH = smem + s * STAGE;
        bf16* aL = aH + SA;
        bf16* bH = aL + SA;
        bf16* bL = bH + SBn;
        if constexpr (!TRANSA) {
            const bf16* gh = Ahi + (long)(rowBase + arow) * lda + kBase + acol;
            const bf16* gl = Alo + (long)(rowBase + arow) * lda + kBase + acol;
            cpa16(aH + arow * LDA_NT + acol, gh);
            cpa16(aH + arow * LDA_NT + acol + 8, gh + 8);
            cpa16(aL + arow * LDA_NT + acol, gl);
            cpa16(aL + arow * LDA_NT + acol + 8, gl + 8);
        } else {
            const bf16* gh = Ahi + (long)(kBase + tkr) * lda + rowBase + tmc;
            const bf16* gl = Alo + (long)(kBase + tkr) * lda + rowBase + tmc;
            cpa16(aH + tkr * LDA_T + tmc, gh);
            cpa16(aH + tkr * LDA_T + tmc + 8, gh + 8);
            cpa16(aL + tkr * LDA_T + tmc, gl);
            cpa16(aL + tkr * LDA_T + tmc + 8, gl + 8);
        }
        cpa16(bH + brow * LDBs + bcol, Bhi + (long)(kBase + brow) * ldb + colBase + bcol);
        cpa16(bL + brow * LDBs + bcol, Blo + (long)(kBase + brow) * ldb + colBase + bcol);
    };

    using ALayout = typename std::conditional<TRANSA, wmma::col_major, wmma::row_major>::type;
    using AFrag = wmma::fragment<wmma::matrix_a, 16, 16, 16, bf16, ALayout>;
    using BFrag = wmma::fragment<wmma::matrix_b, 16, 16, 16, bf16, wmma::row_major>;
    using CFrag = wmma::fragment<wmma::accumulator, 16, 16, 16, float>;

    CFrag acc[2][2];
#pragma unroll
    for (int i = 0; i < 2; i++)
#pragma unroll
        for (int j = 0; j < 2; j++) wmma::fill_fragment(acc[i][j], 0.0f);

    const int KT = K / BK;

    loadStage(0, 0);
    cpa_commit();

    for (int kt = 0; kt < KT; kt++) {
        const int cur = kt & 1;
        if (kt + 1 < KT) {
            loadStage(cur ^ 1, (kt + 1) * BK);
            cpa_commit();
            asm volatile("cp.async.wait_group 1;\n");
        } else {
            asm volatile("cp.async.wait_group 0;\n");
        }
        __syncthreads();

        const bf16* aH = smem + cur * STAGE;
        const bf16* aL = aH + SA;
        const bf16* bH = aL + SA;
        const bf16* bL = bH + SBn;

#pragma unroll
        for (int kk = 0; kk < BK / 16; kk++) {
            AFrag afh[2], afl[2];
            BFrag bfh[2], bfl[2];
#pragma unroll
            for (int i = 0; i < 2; i++) {
                if constexpr (!TRANSA) {
                    wmma::load_matrix_sync(afh[i], aH + (wr * 32 + i * 16) * LDA_NT + kk * 16, LDA_NT);
                    wmma::load_matrix_sync(afl[i], aL + (wr * 32 + i * 16) * LDA_NT + kk * 16, LDA_NT);
                } else {
                    wmma::load_matrix_sync(afh[i], aH + (kk * 16) * LDA_T + wr * 32 + i * 16, LDA_T);
                    wmma::load_matrix_sync(afl[i], aL + (kk * 16) * LDA_T + wr * 32 + i * 16, LDA_T);
                }
            }
#pragma unroll
            for (int j = 0; j < 2; j++) {
                wmma::load_matrix_sync(bfh[j], bH + (kk * 16) * LDBs + wc * 32 + j * 16, LDBs);
                wmma::load_matrix_sync(bfl[j], bL + (kk * 16) * LDBs + wc * 32 + j * 16, LDBs);
            }
#pragma unroll
            for (int i = 0; i < 2; i++)
#pragma unroll
                for (int j = 0; j < 2; j++) {
                    wmma::mma_sync(acc[i][j], afh[i], bfl[j], acc[i][j]);
                    wmma::mma_sync(acc[i][j], afl[i], bfh[j], acc[i][j]);
                    wmma::mma_sync(acc[i][j], afh[i], bfh[j], acc[i][j]);
                }
        }
        __syncthreads();
    }

    // ------------- epilogue (patch through smem; smem free after loop) -----
    float* patch = (float*)smem + warpId * 16 * 20;
    const int rr = lane >> 1;
    const int cc = (lane & 1) * 8;
#pragma unroll
    for (int i = 0; i < 2; i++)
#pragma unroll
        for (int j = 0; j < 2; j++) {
            wmma::store_matrix_sync(patch, acc[i][j], 20, wmma::mem_row_major);
            __syncwarp();
            long gr = rowBase + wr * 32 + i * 16 + rr;
            long gc = colBase + wc * 32 + j * 16 + cc;
            float vals[8];
#pragma unroll
            for (int q = 0; q < 8; q++) vals[q] = patch[rr * 20 + cc + q];
            if constexpr (EPI == EPI_RELU) {
#pragma unroll
                for (int q = 0; q < 8; q++) vals[q] = fmaxf(vals[q], 0.0f);
            } else if constexpr (EPI == EPI_RELU_MUL) {
                uint4 xhu = *(const uint4*)(AuxHi + gr * ldc + gc);
                uint4 xlu = *(const uint4*)(AuxLo + gr * ldc + gc);
                const bf16* xh = (const bf16*)&xhu;
                const bf16* xl = (const bf16*)&xlu;
#pragma unroll
                for (int q = 0; q < 8; q++)
                    vals[q] = fmaxf(vals[q], 0.0f) *
                              (__bfloat162float(xh[q]) + __bfloat162float(xl[q]));
            }
            if constexpr (WLO) {
                bf16 h[8], l[8];
#pragma unroll
                for (int q = 0; q < 8; q++) bsplit(vals[q], h[q], l[q]);
                *(uint4*)(Chi + (long)bz * sC + gr * ldc + gc) = *(uint4*)h;
                *(uint4*)(Clo + (long)bz * sC + gr * ldc + gc) = *(uint4*)l;
            } else {
                *(float4*)(Cf + (long)bz * sC + gr * ldc + gc) =
                    make_float4(vals[0], vals[1], vals[2], vals[3]);
                *(float4*)(Cf + (long)bz * sC + gr * ldc + gc + 4) =
                    make_float4(vals[4], vals[5], vals[6], vals[7]);
            }
            __syncwarp();
        }
}

// ---------------- launch -----------------------------------------------
extern "C" void kernel_launch(void* const* d_in, const int* in_sizes, int n_in,
                              void* d_out, int out_size) {
    const int* idx = (const int*)d_in[0];
    const float* emb = (const float*)d_in[1];
    const float* Dx = (const float*)d_in[2];
    const float* Dy = (const float*)d_in[3];
    const float* E = (const float*)d_in[4];
    const float* readout = (const float*)d_in[5];
    float* out = (float*)d_out;

    bf16 *vh, *vl, *xh, *xl, *kvh, *kvl, *ah, *al, *yh, *yl;
    bf16 *dxh, *dxl, *dyh, *dyl, *eh, *el, *rh, *rl;
    float* t;
    cudaGetSymbolAddress((void**)&vh, g_v_hi);
    cudaGetSymbolAddress((void**)&vl, g_v_lo);
    cudaGetSymbolAddress((void**)&xh, g_x_hi);
    cudaGetSymbolAddress((void**)&xl, g_x_lo);
    cudaGetSymbolAddress((void**)&kvh, g_kv_hi);
    cudaGetSymbolAddress((void**)&kvl, g_kv_lo);
    cudaGetSymbolAddress((void**)&ah, g_a_hi);
    cudaGetSymbolAddress((void**)&al, g_a_lo);
    cudaGetSymbolAddress((void**)&yh, g_y_hi);
    cudaGetSymbolAddress((void**)&yl, g_y_lo);
    cudaGetSymbolAddress((void**)&t, g_t);
    cudaGetSymbolAddress((void**)&dxh, g_Dx_hi);
    cudaGetSymbolAddress((void**)&dxl, g_Dx_lo);
    cudaGetSymbolAddress((void**)&dyh, g_Dy_hi);
    cudaGetSymbolAddress((void**)&dyl, g_Dy_lo);
    cudaGetSymbolAddress((void**)&eh, g_E_hi);
    cudaGetSymbolAddress((void**)&el, g_E_lo);
    cudaGetSymbolAddress((void**)&rh, g_R_hi);
    cudaGetSymbolAddress((void**)&rl, g_R_lo);

    cudaFuncSetAttribute(gemm_bf16x3<false, EPI_RELU, true>,
                         cudaFuncAttributeMaxDynamicSharedMemorySize, SMEM_NT_BYTES);
    cudaFuncSetAttribute(gemm_bf16x3<true, EPI_NONE, true>,
                         cudaFuncAttributeMaxDynamicSharedMemorySize, SMEM_T_BYTES);
    cudaFuncSetAttribute(gemm_bf16x3<false, EPI_NONE, true>,
                         cudaFuncAttributeMaxDynamicSharedMemorySize, SMEM_NT_BYTES);
    cudaFuncSetAttribute(gemm_bf16x3<false, EPI_RELU_MUL, true>,
                         cudaFuncAttributeMaxDynamicSharedMemorySize, SMEM_NT_BYTES);
    cudaFuncSetAttribute(gemm_bf16x3<false, EPI_NONE, false>,
                         cudaFuncAttributeMaxDynamicSharedMemorySize, SMEM_NT_BYTES);

    // split weights once per launch (deterministic)
    split_kernel<<<(Dd * Nn) / 2048, 256>>>(Dx, dxh, dxl);
    split_kernel<<<(Dd * Nn) / 2048, 256>>>(Dy, dyh, dyl);
    split_kernel<<<(Nn * Dd) / 2048, 256>>>(E, eh, el);
    split_kernel<<<(Dd * Vv) / 2048, 256>>>(readout, rh, rl);

    gather_kernel<<<BSROWS, 256>>>(idx, emb, vh, vl);

    for (int l = 0; l < NLAYERS; l++) {
        // x = relu(v @ Dx)
        gemm_bf16x3<false, EPI_RELU, true><<<dim3(Nn / BN, BSROWS / BM, 1), 256, SMEM_NT_BYTES>>>(
            vh, vl, dxh, dxl, nullptr, xh, xl, nullptr, nullptr, BSROWS, Nn, Dd, 0, 0, 0);

        // kv = x^T @ v per batch
        gemm_bf16x3<true, EPI_NONE, true><<<dim3(Dd / BN, Nn / BM, Bb), 256, SMEM_T_BYTES>>>(
            xh, xl, vh, vl, nullptr, kvh, kvl, nullptr, nullptr, Nn, Dd, Ss,
            (long)Ss * Nn, (long)Ss * Dd, (long)Nn * Dd);

        // a = x @ kv per batch
        gemm_bf16x3<false, EPI_NONE, true><<<dim3(Dd / BN, Ss / BM, Bb), 256, SMEM_NT_BYTES>>>(
            xh, xl, kvh, kvl, nullptr, ah, al, nullptr, nullptr, Ss, Dd, Nn,
            (long)Ss * Nn, (long)Nn * Dd, (long)Ss * Dd);

        // y = relu(a @ Dy) * x
        gemm_bf16x3<false, EPI_RELU_MUL, true><<<dim3(Nn / BN, BSROWS / BM, 1), 256, SMEM_NT_BYTES>>>(
            ah, al, dyh, dyl, nullptr, yh, yl, xh, xl, BSROWS, Nn, Dd, 0, 0, 0);

        // t = y @ E (fp32 out)
        gemm_bf16x3<false, EPI_NONE, false><<<dim3(Dd / BN, BSROWS / BM, 1), 256, SMEM_NT_BYTES>>>(
            yh, yl, eh, el, t, nullptr, nullptr, nullptr, nullptr, BSROWS, Dd, Nn, 0, 0, 0);

        // v = LN(v + LN(t))
        ln_res_ln_kernel<<<BSROWS, 256>>>(vh, vl, t);
    }

    // out = v @ readout (fp32 out, 3-term)
    gemm_bf16x3<false, EPI_NONE, false><<<dim3(Vv / BN, BSROWS / BM, 1), 256, SMEM_NT_BYTES>>>(
        vh, vl, rh, rl, out, nullptr, nullptr, nullptr, nullptr, BSROWS, Vv, Dd, 0, 0, 0);
}